// round 3
// baseline (speedup 1.0000x reference)
#include <cuda_runtime.h>
#include <cstdint>

#define BB      32
#define PP      10208
#define PP_PAD  10240
#define CC      81
#define FG      80
#define PRE_K   400
#define MAXDET  100
#define SELCAP  2048
#define KEYCAP  2048
#define NBINS   4096
#define CONF    0.01f
#define NMST    0.45f
#define Wf      1280.0f
#define Hf      1024.0f
#define OFFC    1281.0f

// ---------------- global scratch ----------------
__device__ float g_pmax[BB * PP];
__device__ float g_cscore[BB * SELCAP * FG];

// order-preserving float<->uint maps (for integer max-reduce)
__device__ __forceinline__ unsigned f2ord(float f) {
    unsigned u = __float_as_uint(f);
    return (u & 0x80000000u) ? ~u : (u | 0x80000000u);
}
__device__ __forceinline__ float ord2f(unsigned v) {
    unsigned u = (v & 0x80000000u) ? (v ^ 0x80000000u) : ~v;
    return __uint_as_float(u);
}

// ---------------- K1: per-prior max fg score = 1/sum(exp(xi - mf)) ---------
__global__ void k1_priormax(const float* __restrict__ logits) {
    int gw   = (blockIdx.x * blockDim.x + threadIdx.x) >> 5;
    int lane = threadIdx.x & 31;
    if (gw >= BB * PP) return;
    const float* row = logits + (size_t)gw * CC;
    float x0 = __ldg(row + lane);
    float x1 = __ldg(row + 32 + lane);
    float x2 = (lane < CC - 64) ? __ldg(row + 64 + lane) : -3.0e38f;
    float xf = fmaxf((lane == 0) ? -3.0e38f : x0, fmaxf(x1, x2));  // fg only
    float mf = ord2f(__reduce_max_sync(0xffffffffu, f2ord(xf)));
    float s = __expf(x0 - mf) + __expf(x1 - mf) +
              ((lane < CC - 64) ? __expf(x2 - mf) : 0.0f);
#pragma unroll
    for (int o = 16; o; o >>= 1) s += __shfl_xor_sync(0xffffffffu, s, o);
    if (lane == 0) g_pmax[gw] = __fdividef(1.0f, s);
}

// ---------------- smem layout -------------------
#define OFF_HIST   0
#define OFF_SELIDX 16384
#define OFF_KEYS   24576
#define OFF_F      40960
#define OFF_CL     56960
#define OFF_MASK   58560
#define DYN_BYTES  79360

// warp-aggregated histogram add (all 32 lanes must reach this)
__device__ __forceinline__ void whist(unsigned* hist, unsigned bin, bool valid) {
    unsigned key = valid ? bin : 0xffffffffu;
    unsigned peers = __match_any_sync(0xffffffffu, key);
    if (valid && ((unsigned)(__ffs(peers) - 1) == (threadIdx.x & 31u)))
        atomicAdd(&hist[bin], __popc(peers));
}

// boundary finder: largest bin Bb with count(bins >= Bb) >= T; *s_above = count strictly above
__device__ __forceinline__ int boundary(const unsigned* __restrict__ h, int T,
                                        int* s_minR, unsigned* s_above,
                                        unsigned* s_wsum) {
    int t = threadIdx.x, lane = t & 31, w = t >> 5;
    if (t == 0) { *s_minR = 0x7fffffff; *s_above = 0u; }
    __syncthreads();
    int base = 4095 - 4 * t;
    unsigned c0 = h[base], c1 = h[base - 1], c2 = h[base - 2], c3 = h[base - 3];
    unsigned part = c0 + c1 + c2 + c3;
    unsigned v = part;
#pragma unroll
    for (int o = 1; o < 32; o <<= 1) {
        unsigned u = __shfl_up_sync(0xffffffffu, v, o);
        if (lane >= o) v += u;
    }
    if (lane == 31) s_wsum[w] = v;
    __syncthreads();
    if (w == 0) {
        unsigned x = s_wsum[lane];
#pragma unroll
        for (int o = 1; o < 32; o <<= 1) {
            unsigned u = __shfl_up_sync(0xffffffffu, x, o);
            if (lane >= o) x += u;
        }
        s_wsum[lane] = x;
    }
    __syncthreads();
    unsigned excl = ((w > 0) ? s_wsum[w - 1] : 0u) + (v - part);
    unsigned cum = excl, myAbove = 0;
    int myR = 0x7fffffff;
    unsigned cs[4] = {c0, c1, c2, c3};
#pragma unroll
    for (int i2 = 0; i2 < 4; i2++) {
        unsigned prev = cum;
        cum += cs[i2];
        if (myR == 0x7fffffff && cum >= (unsigned)T) { myR = 4 * t + i2; myAbove = prev; }
    }
    if (myR != 0x7fffffff) atomicMin(s_minR, myR);
    __syncthreads();
    int r = *s_minR;
    if (r == myR && myR != 0x7fffffff) *s_above = myAbove;
    __syncthreads();
    return (r == 0x7fffffff) ? 0 : (4095 - r);
}

// bitonic sort n (pow2 >= 64) 64-bit keys ascending; block = 1024 thr
__device__ __forceinline__ void bitonic(unsigned long long* keys, int n) {
    int t = threadIdx.x;
    for (int base = t; base < n; base += 1024) {
        unsigned long long key = keys[base];
#pragma unroll
        for (int k2 = 2; k2 <= 32; k2 <<= 1) {
            bool up = ((base & k2) == 0);
#pragma unroll
            for (int j = k2 >> 1; j >= 1; j >>= 1) {
                unsigned long long other = __shfl_xor_sync(0xffffffffu, key, j);
                bool keepSmall = (((base & j) == 0) == up);
                bool take = keepSmall ? (other < key) : (other > key);
                if (take) key = other;
            }
        }
        keys[base] = key;
    }
    __syncthreads();
    for (int k = 64; k <= n; k <<= 1) {
        for (int j = k >> 1; j >= 32; j >>= 1) {
            for (int u = t; u < (n >> 1); u += 1024) {
                int i = ((u & ~(j - 1)) << 1) | (u & (j - 1));
                int p = i | j;
                unsigned long long a = keys[i], bk = keys[p];
                bool up = ((i & k) == 0);
                if ((a > bk) == up) { keys[i] = bk; keys[p] = a; }
            }
            __syncthreads();
        }
        for (int base = t; base < n; base += 1024) {
            unsigned long long key = keys[base];
            bool up = ((base & k) == 0);
#pragma unroll
            for (int j = 16; j >= 1; j >>= 1) {
                unsigned long long other = __shfl_xor_sync(0xffffffffu, key, j);
                bool keepSmall = (((base & j) == 0) == up);
                bool take = keepSmall ? (other < key) : (other > key);
                if (take) key = other;
            }
            keys[base] = key;
        }
        __syncthreads();
    }
}

// -------- fused per-batch: select -> scores -> top-400 -> NMS -> out -------
__global__ void __launch_bounds__(1024) k2_fused(const float* __restrict__ logits,
                                                 const float* __restrict__ bbox,
                                                 const float* __restrict__ priors,
                                                 float* __restrict__ out) {
    extern __shared__ unsigned char dyn[];
    unsigned*           hist   = (unsigned*)(dyn + OFF_HIST);
    int*                selidx = (int*)(dyn + OFF_SELIDX);
    unsigned long long* keys   = (unsigned long long*)(dyn + OFF_KEYS);
    float*              pmaxc  = (float*)(dyn + OFF_KEYS);   // alias, phase A only
    float* F   = (float*)(dyn + OFF_F);
    float *ox1 = F, *oy1 = F + 400, *ox2 = F + 800, *oy2 = F + 1200, *ar = F + 1600;
    float *bx1 = F + 2000, *by1 = F + 2400, *bx2 = F + 2800, *by2 = F + 3200, *tv = F + 3600;
    int*       cl   = (int*)(dyn + OFF_CL);
    unsigned*  mask = (unsigned*)(dyn + OFF_MASK);

    __shared__ unsigned s_wsum[32];
    __shared__ int s_minR, s_cnt;
    __shared__ unsigned s_above;
    __shared__ unsigned initm[13], finm[13];
    __shared__ int fi[MAXDET], warpcnt[32], warpoff[33];

    int b = blockIdx.x, t = threadIdx.x, lane = t & 31, w = t >> 5;
    unsigned lt = (1u << lane) - 1u;

    // ---------- phase A: covering prior selection (T = 512) ----------
    if (t == 0) s_cnt = 0;
    for (int i = t; i < NBINS; i += 1024) hist[i] = 0u;
    __syncthreads();
    for (int i0 = 0; i0 < PP_PAD; i0 += 1024) {
        int i = i0 + t; bool v = (i < PP);
        float pv = v ? g_pmax[b * PP + i] : 0.0f;
        if (v) pmaxc[i] = pv;
        whist(hist, __float_as_uint(pv) >> 18, v);
    }
    __syncthreads();
    int BbA = boundary(hist, 512, &s_minR, &s_above, s_wsum);
    int needA = 512 - (int)s_above;
    for (int i = t; i < NBINS; i += 1024) hist[i] = 0u;
    __syncthreads();
    for (int i0 = 0; i0 < PP_PAD; i0 += 1024) {
        int i = i0 + t; bool v = (i < PP);
        unsigned bits = v ? __float_as_uint(pmaxc[i]) : 0u;
        whist(hist, (bits >> 6) & 0xFFF, v && ((int)(bits >> 18) == BbA));
    }
    __syncthreads();
    int Bb2A = boundary(hist, needA, &s_minR, &s_above, s_wsum);
    for (int i0 = 0; i0 < PP_PAD; i0 += 1024) {
        int i = i0 + t; bool v = (i < PP);
        unsigned bits = v ? __float_as_uint(pmaxc[i]) : 0u;
        int key = (int)(bits >> 18);
        bool sel = v && ((key > BbA) || (key == BbA && (int)((bits >> 6) & 0xFFF) >= Bb2A));
        unsigned ball = __ballot_sync(0xffffffffu, sel);
        int base = 0;
        if (lane == 0 && ball) base = atomicAdd(&s_cnt, __popc(ball));
        base = __shfl_sync(0xffffffffu, base, 0);
        if (sel) {
            int p = base + __popc(ball & lt);
            if (p < SELCAP) selidx[p] = i;
        }
    }
    __syncthreads();
    int ns = min(s_cnt, SELCAP);

    // ---------- phase B: exact softmax for selected priors ----------
    for (int i = t; i < NBINS; i += 1024) hist[i] = 0u;
    __syncthreads();
    for (int slot = w; slot < ns; slot += 32) {
        int prior = selidx[slot];
        const float* row = logits + ((size_t)b * PP + prior) * CC;
        float x0 = __ldg(row + lane);
        float x1 = __ldg(row + 32 + lane);
        float x2 = (lane < CC - 64) ? __ldg(row + 64 + lane) : -1e30f;
        float m = fmaxf(fmaxf(x0, x1), x2);
#pragma unroll
        for (int o = 16; o; o >>= 1) m = fmaxf(m, __shfl_xor_sync(0xffffffffu, m, o));
        float s = expf(x0 - m) + expf(x1 - m) + ((lane < CC - 64) ? expf(x2 - m) : 0.0f);
#pragma unroll
        for (int o = 16; o; o >>= 1) s += __shfl_xor_sync(0xffffffffu, s, o);
        float* outp = &g_cscore[((size_t)b * SELCAP + slot) * FG];
        float sc0 = expf(x0 - m) / s;
        float sc1 = expf(x1 - m) / s;
        float sc2 = (lane < CC - 64) ? (expf(x2 - m) / s) : 0.0f;
        if (lane > 0) outp[lane - 1] = sc0;
        outp[31 + lane] = sc1;
        if (lane < CC - 64) outp[63 + lane] = sc2;
        whist(hist, __float_as_uint(sc0) >> 18, lane > 0);
        whist(hist, __float_as_uint(sc1) >> 18, true);
        whist(hist, __float_as_uint(sc2) >> 18, lane < CC - 64);
    }
    __syncthreads();

    // ---------- phase C: two-level threshold for exact top-400 ----------
    int n80 = ns * FG;
    int n80p = (n80 + 1023) & ~1023;
    const float* cs = &g_cscore[(size_t)b * SELCAP * FG];
    int BbS = boundary(hist, PRE_K, &s_minR, &s_above, s_wsum);
    int needS = PRE_K - (int)s_above;
    for (int i = t; i < NBINS; i += 1024) hist[i] = 0u;
    __syncthreads();
    for (int i0 = 0; i0 < n80p; i0 += 1024) {
        int i = i0 + t; bool v = (i < n80);
        unsigned bits = v ? __float_as_uint(cs[i]) : 0u;
        whist(hist, (bits >> 6) & 0xFFF, v && ((int)(bits >> 18) == BbS));
    }
    __syncthreads();
    int Bb2S = boundary(hist, needS, &s_minR, &s_above, s_wsum);

    // ---------- phase D: collect + sort ----------
    if (t == 0) s_cnt = 0;
    for (int i = t; i < KEYCAP; i += 1024) keys[i] = 0xFFFFFFFFFFFFFFFFull;
    __syncthreads();
    for (int i0 = 0; i0 < n80p; i0 += 1024) {
        int i = i0 + t; bool v = (i < n80);
        unsigned bits = v ? __float_as_uint(cs[i]) : 0u;
        int key = (int)(bits >> 18);
        bool sel = v && ((key > BbS) || (key == BbS && (int)((bits >> 6) & 0xFFF) >= Bb2S));
        unsigned ball = __ballot_sync(0xffffffffu, sel);
        int base = 0;
        if (lane == 0 && ball) base = atomicAdd(&s_cnt, __popc(ball));
        base = __shfl_sync(0xffffffffu, base, 0);
        if (sel) {
            int p = base + __popc(ball & lt);
            if (p < KEYCAP) {
                int slot = i / FG, c = i - slot * FG;
                unsigned fidx = (unsigned)selidx[slot] * FG + (unsigned)c;
                keys[p] = ((unsigned long long)(~bits) << 32) | (unsigned long long)fidx;
            }
        }
    }
    __syncthreads();
    int cnt = min(s_cnt, KEYCAP);
    int sortn = (cnt <= 512) ? 512 : (cnt <= 1024 ? 1024 : 2048);
    bitonic(keys, sortn);

    // ---------- phase E: decode + bitmask NMS + stable top-100 ----------
    for (int i = t; i < PRE_K * 13; i += 1024) mask[i] = 0u;
    if (t < PRE_K) {
        unsigned long long key = keys[t];
        unsigned bits = ~(unsigned)(key >> 32);
        float v = __uint_as_float(bits);
        int fidx = (int)(key & 0xFFFFFFFFull);
        if (fidx < 0 || fidx >= PP * FG) { fidx = 0; v = 0.0f; }
        int prior = fidx / FG;
        int c = fidx - prior * FG + 1;
        tv[t] = v; cl[t] = c;
        const float* L  = bbox   + ((size_t)b * PP + prior) * 4;
        const float* Pr = priors + (size_t)prior * 4;
        float px = Pr[0], py = Pr[1], pw = Pr[2], ph = Pr[3];
        float cx = L[0] * 0.1f * pw + px;
        float cy = L[1] * 0.1f * ph + py;
        float sw = expf(L[2] * 0.2f) * pw;
        float sh = expf(L[3] * 0.2f) * ph;
        float X1 = (cx - sw * 0.5f) * Wf, Y1 = (cy - sh * 0.5f) * Hf;
        float X2 = (cx + sw * 0.5f) * Wf, Y2 = (cy + sh * 0.5f) * Hf;
        bx1[t] = X1; by1[t] = Y1; bx2[t] = X2; by2[t] = Y2;
        float off = (float)c * OFFC;
        float a1 = X1 + off, a2 = Y1 + off, a3 = X2 + off, a4 = Y2 + off;
        ox1[t] = a1; oy1[t] = a2; ox2[t] = a3; oy2[t] = a4;
        ar[t] = (a3 - a1) * (a4 - a2);
    }
    __syncthreads();
    if (w < 13) {
        bool rm = true;
        if (t < PRE_K) rm = !(tv[t] > CONF);
        unsigned ball = __ballot_sync(0xffffffffu, rm);
        if (lane == 0) initm[w] = ball;
    }
    __syncthreads();
    for (int idx = t; idx < PRE_K * PRE_K; idx += 1024) {
        int i = idx / PRE_K, j = idx - i * PRE_K;
        if (j > i) {
            float ltx = fmaxf(ox1[i], ox1[j]);
            float lty = fmaxf(oy1[i], oy1[j]);
            float rbx = fminf(ox2[i], ox2[j]);
            float rby = fminf(oy2[i], oy2[j]);
            float wv = fmaxf(rbx - ltx, 0.0f), hv = fmaxf(rby - lty, 0.0f);
            float inter = wv * hv;
            float iou = inter / (ar[i] + ar[j] - inter + 1e-9f);
            if (iou > NMST) atomicOr(&mask[i * 13 + (j >> 5)], 1u << (j & 31));
        }
    }
    __syncthreads();
    if (w == 0) {  // serial greedy walk; speculative OR, chain = shfl + select
        unsigned remv = (lane < 13) ? initm[lane] : 0u;
        unsigned nextrow = (lane < 13) ? mask[lane] : 0u;
        for (int i = 0; i < PRE_K; i++) {
            unsigned row = nextrow;
            if (i + 1 < PRE_K) nextrow = (lane < 13) ? mask[(i + 1) * 13 + lane] : 0u;
            unsigned cand = remv | row;
            unsigned word = __shfl_sync(0xffffffffu, remv, i >> 5);
            remv = (word & (1u << (i & 31))) ? remv : cand;
        }
        if (lane < 13) finm[lane] = remv;
    }
    __syncthreads();
    bool kp = false;
    if (t < PRE_K) kp = !((finm[t >> 5] >> (t & 31)) & 1u);
    unsigned ball = __ballot_sync(0xffffffffu, kp);
    if (lane == 0) warpcnt[w] = __popc(ball);
    __syncthreads();
    if (t == 0) {
        int acc = 0;
        for (int i = 0; i < 32; i++) { warpoff[i] = acc; acc += warpcnt[i]; }
        warpoff[32] = acc;
    }
    __syncthreads();
    int nk = warpoff[32];
    if (t < PRE_K) {
        int rk = warpoff[w] + __popc(ball & lt);
        int pos = kp ? rk : nk + (t - rk);
        if (pos < MAXDET) fi[pos] = t;
    }
    __syncthreads();
    if (t < MAXDET) {
        int j = fi[t];
        bool kj = !((finm[j >> 5] >> (j & 31)) & 1u);
        int base = (b * MAXDET + t) * 4;
        out[base + 0] = bx1[j];
        out[base + 1] = by1[j];
        out[base + 2] = bx2[j];
        out[base + 3] = by2[j];
        out[BB * MAXDET * 4 + b * MAXDET + t] = (float)cl[j];
        out[BB * MAXDET * 5 + b * MAXDET + t] = kj ? tv[j] : 0.0f;
    }
}

// ------------------------------ launcher -----------------------------------
extern "C" void kernel_launch(void* const* d_in, const int* in_sizes, int n_in,
                              void* d_out, int out_size) {
    const float* logits = (const float*)d_in[0];
    const float* bbox   = (const float*)d_in[1];
    const float* priors = (const float*)d_in[2];
    float* out = (float*)d_out;

    cudaFuncSetAttribute(k2_fused, cudaFuncAttributeMaxDynamicSharedMemorySize,
                         DYN_BYTES);

    int totalThreads = BB * PP * 32;
    k1_priormax<<<(totalThreads + 255) / 256, 256>>>(logits);
    k2_fused<<<BB, 1024, DYN_BYTES>>>(logits, bbox, priors, out);
}

// round 4
// speedup vs baseline: 1.6756x; 1.6756x over previous
#include <cuda_runtime.h>
#include <cstdint>
#include <math.h>

#define BB      32
#define PP      10208
#define PP_PAD  10240
#define CC      81
#define FG      80
#define PRE_K   400
#define MAXDET  100
#define SELCAP  2048
#define KEYCAP  4096
#define NBINS   4096
#define CONF    0.01f
#define NMST    0.45f
#define Wf      1280.0f
#define Hf      1024.0f
#define OFFC    1281.0f
#define G       8          // rows per warp in k1

// ---------------- global scratch ----------------
__device__ float g_pmax[BB * PP];

// order-preserving float<->uint maps
__device__ __forceinline__ unsigned f2ord(float f) {
    unsigned u = __float_as_uint(f);
    return (u & 0x80000000u) ? ~u : (u | 0x80000000u);
}
__device__ __forceinline__ float ord2f(unsigned v) {
    unsigned u = (v & 0x80000000u) ? (v ^ 0x80000000u) : ~v;
    return __uint_as_float(u);
}

// ------- K1: per-prior max fg score = 1/sum(exp(xi-mf)); 8 rows/warp -------
__global__ void k1_priormax(const float* __restrict__ logits) {
    int wid  = (blockIdx.x * blockDim.x + threadIdx.x) >> 5;
    int lane = threadIdx.x & 31;
    int row  = wid * G;
    if (row >= BB * PP) return;
    const float* p = logits + (size_t)row * CC;
    float a0 = __ldg(p + lane);
    float a1 = __ldg(p + 32 + lane);
    float a2 = (lane < 17) ? __ldg(p + 64 + lane) : -3.0e38f;
#pragma unroll
    for (int g = 0; g < G; g++) {
        float x0 = a0, x1 = a1, x2 = a2;
        if (g + 1 < G) {                    // prefetch next row before reducing
            p += CC;
            a0 = __ldg(p + lane);
            a1 = __ldg(p + 32 + lane);
            a2 = (lane < 17) ? __ldg(p + 64 + lane) : -3.0e38f;
        }
        float xf = fmaxf((lane == 0) ? -3.0e38f : x0, fmaxf(x1, x2));
        float mf = ord2f(__reduce_max_sync(0xffffffffu, f2ord(xf)));
        float s = __expf(x0 - mf) + __expf(x1 - mf) +
                  ((lane < 17) ? __expf(x2 - mf) : 0.0f);
#pragma unroll
        for (int o = 16; o; o >>= 1) s += __shfl_xor_sync(0xffffffffu, s, o);
        if (lane == 0) g_pmax[row + g] = __fdividef(1.0f, s);
    }
}

// ---------------- smem layout for fused kernel ----------------
#define OFF_HIST   0        // 4096 u32   = 16384
#define OFF_SELIDX 16384    // 2048 int   =  8192
#define OFF_KEYS   24576    // 4096 u64   = 32768
#define OFF_F      57344    // 4000 f32   = 16000
#define OFF_CL     73344    //  400 int   =  1600
#define OFF_MASK   74944    // 5200 u32   = 20800
#define DYN_BYTES  95744

// boundary: largest bin Bb with count(bins >= Bb) >= T; *s_above = count strictly above
__device__ __forceinline__ int boundary(const unsigned* __restrict__ h, int T,
                                        int* s_minR, unsigned* s_above,
                                        unsigned* s_wsum) {
    int t = threadIdx.x, lane = t & 31, w = t >> 5;
    __syncthreads();                         // protect prior reads of s_above
    if (t == 0) { *s_minR = 0x7fffffff; *s_above = 0u; }
    __syncthreads();
    int base = 4095 - 4 * t;
    unsigned c0 = h[base], c1 = h[base - 1], c2 = h[base - 2], c3 = h[base - 3];
    unsigned part = c0 + c1 + c2 + c3;
    unsigned v = part;
#pragma unroll
    for (int o = 1; o < 32; o <<= 1) {
        unsigned u = __shfl_up_sync(0xffffffffu, v, o);
        if (lane >= o) v += u;
    }
    if (lane == 31) s_wsum[w] = v;
    __syncthreads();
    if (w == 0) {
        unsigned x = s_wsum[lane];
#pragma unroll
        for (int o = 1; o < 32; o <<= 1) {
            unsigned u = __shfl_up_sync(0xffffffffu, x, o);
            if (lane >= o) x += u;
        }
        s_wsum[lane] = x;
    }
    __syncthreads();
    unsigned excl = ((w > 0) ? s_wsum[w - 1] : 0u) + (v - part);
    unsigned cum = excl, myAbove = 0;
    int myR = 0x7fffffff;
    unsigned cs[4] = {c0, c1, c2, c3};
#pragma unroll
    for (int i2 = 0; i2 < 4; i2++) {
        unsigned prev = cum;
        cum += cs[i2];
        if (myR == 0x7fffffff && cum >= (unsigned)T) { myR = 4 * t + i2; myAbove = prev; }
    }
    if (myR != 0x7fffffff) atomicMin(s_minR, myR);
    __syncthreads();
    int r = *s_minR;
    if (r == myR && myR != 0x7fffffff) *s_above = myAbove;
    __syncthreads();
    return (r == 0x7fffffff) ? 0 : (4095 - r);
}

// bitonic sort n (pow2 >= 64) u64 keys ascending; block = 1024 thr
__device__ __forceinline__ void bitonic(unsigned long long* keys, int n) {
    int t = threadIdx.x;
    for (int base = t; base < n; base += 1024) {
        unsigned long long key = keys[base];
#pragma unroll
        for (int k2 = 2; k2 <= 32; k2 <<= 1) {
            bool up = ((base & k2) == 0);
#pragma unroll
            for (int j = k2 >> 1; j >= 1; j >>= 1) {
                unsigned long long other = __shfl_xor_sync(0xffffffffu, key, j);
                bool keepSmall = (((base & j) == 0) == up);
                bool take = keepSmall ? (other < key) : (other > key);
                if (take) key = other;
            }
        }
        keys[base] = key;
    }
    __syncthreads();
    for (int k = 64; k <= n; k <<= 1) {
        for (int j = k >> 1; j >= 32; j >>= 1) {
            for (int u = t; u < (n >> 1); u += 1024) {
                int i = ((u & ~(j - 1)) << 1) | (u & (j - 1));
                int p = i | j;
                unsigned long long a = keys[i], bk = keys[p];
                bool up = ((i & k) == 0);
                if ((a > bk) == up) { keys[i] = bk; keys[p] = a; }
            }
            __syncthreads();
        }
        for (int base = t; base < n; base += 1024) {
            unsigned long long key = keys[base];
            bool up = ((base & k) == 0);
#pragma unroll
            for (int j = 16; j >= 1; j >>= 1) {
                unsigned long long other = __shfl_xor_sync(0xffffffffu, key, j);
                bool keepSmall = (((base & j) == 0) == up);
                bool take = keepSmall ? (other < key) : (other > key);
                if (take) key = other;
            }
            keys[base] = key;
        }
        __syncthreads();
    }
}

// -------- fused per-batch: select -> scores -> top-400 -> NMS -> out -------
__global__ void __launch_bounds__(1024) k2_fused(const float* __restrict__ logits,
                                                 const float* __restrict__ bbox,
                                                 const float* __restrict__ priors,
                                                 float* __restrict__ out) {
    extern __shared__ unsigned char dyn[];
    unsigned*           hist   = (unsigned*)(dyn + OFF_HIST);
    int*                selidx = (int*)(dyn + OFF_SELIDX);
    unsigned long long* keys   = (unsigned long long*)(dyn + OFF_KEYS);
    float* F   = (float*)(dyn + OFF_F);
    float *ox1 = F, *oy1 = F + 400, *ox2 = F + 800, *oy2 = F + 1200, *ar = F + 1600;
    float *bx1 = F + 2000, *by1 = F + 2400, *bx2 = F + 2800, *by2 = F + 3200, *tv = F + 3600;
    int*       cl   = (int*)(dyn + OFF_CL);
    unsigned*  mask = (unsigned*)(dyn + OFF_MASK);

    __shared__ unsigned s_wsum[32];
    __shared__ int s_minR, s_cnt, s_cnt2;
    __shared__ unsigned s_above;
    __shared__ unsigned initm[13], finm[13];
    __shared__ int fi[MAXDET], warpcnt[32], warpoff[33];

    int b = blockIdx.x, t = threadIdx.x, lane = t & 31, w = t >> 5;
    unsigned lt = (1u << lane) - 1u;
    const float* pmaxb = g_pmax + b * PP;

    // ---- phase A: pmax histogram -> threshold tau ~ 400th-largest pmax ----
    if (t == 0) { s_cnt = 0; s_cnt2 = 0; }
    for (int i = t; i < NBINS; i += 1024) { hist[i] = 0u; keys[i] = 0xFFFFFFFFFFFFFFFFull; }
    __syncthreads();
    for (int i = t; i < PP; i += 1024)
        atomicAdd(&hist[__float_as_uint(pmaxb[i]) >> 18], 1u);
    __syncthreads();
    int BbA = boundary(hist, PRE_K, &s_minR, &s_above, s_wsum);
    int needA = PRE_K - (int)s_above;
    for (int i = t; i < NBINS; i += 1024) hist[i] = 0u;
    __syncthreads();
    for (int i = t; i < PP; i += 1024) {
        unsigned bits = __float_as_uint(pmaxb[i]);
        if ((int)(bits >> 18) == BbA) atomicAdd(&hist[(bits >> 6) & 0xFFF], 1u);
    }
    __syncthreads();
    int Bb2A = boundary(hist, needA, &s_minR, &s_above, s_wsum);
    if (Bb2A > 0) Bb2A--;                 // one fine-bin slack (covers k1 __expf noise)

    // select priors with pmax >= tau
    for (int i0 = 0; i0 < PP_PAD; i0 += 1024) {
        int i = i0 + t; bool v = (i < PP);
        unsigned bits = v ? __float_as_uint(pmaxb[i]) : 0u;
        int key = (int)(bits >> 18);
        bool sel = v && ((key > BbA) || (key == BbA && (int)((bits >> 6) & 0xFFF) >= Bb2A));
        unsigned ball = __ballot_sync(0xffffffffu, sel);
        int base = 0;
        if (lane == 0 && ball) base = atomicAdd(&s_cnt, __popc(ball));
        base = __shfl_sync(0xffffffffu, base, 0);
        if (sel) {
            int p = base + __popc(ball & lt);
            if (p < SELCAP) selidx[p] = i;
        }
    }
    __syncthreads();
    int ns = min(s_cnt, SELCAP);

    // ---- phase B: exact softmax on selected priors; collect scores >= tau ----
    for (int slot = w; slot < ns; slot += 32) {
        int prior = selidx[slot];
        const float* row = logits + ((size_t)b * PP + prior) * CC;
        float x0 = __ldg(row + lane);
        float x1 = __ldg(row + 32 + lane);
        float x2 = (lane < 17) ? __ldg(row + 64 + lane) : -3.0e38f;
        float m = ord2f(__reduce_max_sync(0xffffffffu, f2ord(fmaxf(x0, fmaxf(x1, x2)))));
        float e0 = expf(x0 - m);
        float e1 = expf(x1 - m);
        float e2 = (lane < 17) ? expf(x2 - m) : 0.0f;
        float s = e0 + e1 + e2;
#pragma unroll
        for (int o = 16; o; o >>= 1) s += __shfl_xor_sync(0xffffffffu, s, o);
        float sc0 = e0 / s, sc1 = e1 / s, sc2 = e2 / s;   // exact per-element div
        unsigned b0 = __float_as_uint(sc0), b1 = __float_as_uint(sc1), b2 = __float_as_uint(sc2);
        int k0 = (int)(b0 >> 18), k1v = (int)(b1 >> 18), k2v = (int)(b2 >> 18);
        bool s0 = (lane > 0)  && ((k0 > BbA)  || (k0 == BbA  && (int)((b0 >> 6) & 0xFFF) >= Bb2A));
        bool s1 =                ((k1v > BbA) || (k1v == BbA && (int)((b1 >> 6) & 0xFFF) >= Bb2A));
        bool s2 = (lane < 17) && ((k2v > BbA) || (k2v == BbA && (int)((b2 >> 6) & 0xFFF) >= Bb2A));
        unsigned ba0 = __ballot_sync(0xffffffffu, s0);
        unsigned ba1 = __ballot_sync(0xffffffffu, s1);
        unsigned ba2 = __ballot_sync(0xffffffffu, s2);
        int n0 = __popc(ba0), n1 = __popc(ba1), n2 = __popc(ba2);
        int base = 0;
        if (lane == 0 && (n0 + n1 + n2)) base = atomicAdd(&s_cnt2, n0 + n1 + n2);
        base = __shfl_sync(0xffffffffu, base, 0);
        unsigned fb = (unsigned)prior * FG;
        if (s0) {
            int p = base + __popc(ba0 & lt);
            if (p < KEYCAP) keys[p] = ((unsigned long long)(~b0) << 32) | (fb + lane - 1);
        }
        if (s1) {
            int p = base + n0 + __popc(ba1 & lt);
            if (p < KEYCAP) keys[p] = ((unsigned long long)(~b1) << 32) | (fb + 31 + lane);
        }
        if (s2) {
            int p = base + n0 + n1 + __popc(ba2 & lt);
            if (p < KEYCAP) keys[p] = ((unsigned long long)(~b2) << 32) | (fb + 63 + lane);
        }
    }
    __syncthreads();
    int cnt = min(s_cnt2, KEYCAP);
    int sortn = 512;
    while (sortn < cnt) sortn <<= 1;      // 512/1024/2048/4096
    bitonic(keys, sortn);

    // ---- phase E: decode + bitmask NMS + stable top-100 ----
    for (int i = t; i < PRE_K * 13; i += 1024) mask[i] = 0u;
    if (t < PRE_K) {
        unsigned long long key = keys[t];
        unsigned bits = ~(unsigned)(key >> 32);
        float v = __uint_as_float(bits);
        int fidx = (int)(key & 0xFFFFFFFFull);
        if (fidx < 0 || fidx >= PP * FG) { fidx = 0; v = 0.0f; }
        int prior = fidx / FG;
        int c = fidx - prior * FG + 1;
        tv[t] = v; cl[t] = c;
        const float* L  = bbox   + ((size_t)b * PP + prior) * 4;
        const float* Pr = priors + (size_t)prior * 4;
        float px = Pr[0], py = Pr[1], pw = Pr[2], ph = Pr[3];
        float cx = L[0] * 0.1f * pw + px;
        float cy = L[1] * 0.1f * ph + py;
        float sw = expf(L[2] * 0.2f) * pw;
        float sh = expf(L[3] * 0.2f) * ph;
        float X1 = (cx - sw * 0.5f) * Wf, Y1 = (cy - sh * 0.5f) * Hf;
        float X2 = (cx + sw * 0.5f) * Wf, Y2 = (cy + sh * 0.5f) * Hf;
        bx1[t] = X1; by1[t] = Y1; bx2[t] = X2; by2[t] = Y2;
        float off = (float)c * OFFC;
        float a1 = X1 + off, a2 = Y1 + off, a3 = X2 + off, a4 = Y2 + off;
        ox1[t] = a1; oy1[t] = a2; ox2[t] = a3; oy2[t] = a4;
        ar[t] = (a3 - a1) * (a4 - a2);
    }
    __syncthreads();
    if (w < 13) {
        bool rm = true;
        if (t < PRE_K) rm = !(tv[t] > CONF);
        unsigned ball = __ballot_sync(0xffffffffu, rm);
        if (lane == 0) initm[w] = ball;
    }
    __syncthreads();
    for (int idx = t; idx < PRE_K * PRE_K; idx += 1024) {
        int i = idx / PRE_K, j = idx - i * PRE_K;
        if (j > i) {
            float ltx = fmaxf(ox1[i], ox1[j]);
            float lty = fmaxf(oy1[i], oy1[j]);
            float rbx = fminf(ox2[i], ox2[j]);
            float rby = fminf(oy2[i], oy2[j]);
            float wv = fmaxf(rbx - ltx, 0.0f), hv = fmaxf(rby - lty, 0.0f);
            float inter = wv * hv;
            float iou = inter / (ar[i] + ar[j] - inter + 1e-9f);
            if (iou > NMST) atomicOr(&mask[i * 13 + (j >> 5)], 1u << (j & 31));
        }
    }
    __syncthreads();
    if (w == 0) {   // serial greedy walk; speculative OR, chain = shfl + select
        unsigned remv = (lane < 13) ? initm[lane] : 0u;
        unsigned nextrow = (lane < 13) ? mask[lane] : 0u;
        for (int i = 0; i < PRE_K; i++) {
            unsigned row = nextrow;
            if (i + 1 < PRE_K) nextrow = (lane < 13) ? mask[(i + 1) * 13 + lane] : 0u;
            unsigned cand = remv | row;
            unsigned word = __shfl_sync(0xffffffffu, remv, i >> 5);
            remv = (word & (1u << (i & 31))) ? remv : cand;
        }
        if (lane < 13) finm[lane] = remv;
    }
    __syncthreads();
    bool kp = false;
    if (t < PRE_K) kp = !((finm[t >> 5] >> (t & 31)) & 1u);
    unsigned ball = __ballot_sync(0xffffffffu, kp);
    if (lane == 0) warpcnt[w] = __popc(ball);
    __syncthreads();
    if (t == 0) {
        int acc = 0;
        for (int i = 0; i < 32; i++) { warpoff[i] = acc; acc += warpcnt[i]; }
        warpoff[32] = acc;
    }
    __syncthreads();
    int nk = warpoff[32];
    if (t < PRE_K) {
        int rk = warpoff[w] + __popc(ball & lt);
        int pos = kp ? rk : nk + (t - rk);
        if (pos < MAXDET) fi[pos] = t;
    }
    __syncthreads();
    if (t < MAXDET) {
        int j = fi[t];
        bool kj = !((finm[j >> 5] >> (j & 31)) & 1u);
        int base = (b * MAXDET + t) * 4;
        out[base + 0] = bx1[j];
        out[base + 1] = by1[j];
        out[base + 2] = bx2[j];
        out[base + 3] = by2[j];
        out[BB * MAXDET * 4 + b * MAXDET + t] = (float)cl[j];
        out[BB * MAXDET * 5 + b * MAXDET + t] = kj ? tv[j] : 0.0f;
    }
}

// ------------------------------ launcher -----------------------------------
extern "C" void kernel_launch(void* const* d_in, const int* in_sizes, int n_in,
                              void* d_out, int out_size) {
    const float* logits = (const float*)d_in[0];
    const float* bbox   = (const float*)d_in[1];
    const float* priors = (const float*)d_in[2];
    float* out = (float*)d_out;

    cudaFuncSetAttribute(k2_fused, cudaFuncAttributeMaxDynamicSharedMemorySize,
                         DYN_BYTES);

    int totalWarps = (BB * PP) / G;            // 40832 warps, 8 rows each
    int blocks = (totalWarps * 32 + 255) / 256;
    k1_priormax<<<blocks, 256>>>(logits);
    k2_fused<<<BB, 1024, DYN_BYTES>>>(logits, bbox, priors, out);
}